// round 3
// baseline (speedup 1.0000x reference)
#include <cuda_runtime.h>
#include <cstdint>

// Haar DWT level-1 on x: (8, 64, 512, 512) fp32 -> 4 quadrants (8,64,256,256)
// concatenated in d_out as [ll | lh | hl | hh].
//
// Per thread: one 4x8 input patch (8x float4 streaming loads, front-batched for
// MLP=8) -> eight 2x2 Haar butterflies -> two float4 streaming stores per quadrant.
//
// planes P = 512, H = W = 512, outH = outW = 256
// col-groups per row: 256/4 = 64 ; row-pairs of output rows: 256/2 = 128
// total threads = 512 * 128 * 64 = 4,194,304 = 16384 blocks x 256

__global__ __launch_bounds__(256, 6)
void haar_dwt_kernel(const float* __restrict__ in, float* __restrict__ out) {
    const unsigned idx = blockIdx.x * 256u + threadIdx.x;   // < 4,194,304
    const unsigned tx = idx & 63u;             // group of 4 output cols (0..63)
    const unsigned oy = ((idx >> 6) & 127u) * 2u;  // output row base (0,2,..,254)
    const unsigned p  = idx >> 13;             // plane (0..511)

    // Input: rows 2*oy .. 2*oy+3 of plane p; cols 8tx..8tx+7 (two float4 per row).
    const float4* __restrict__ in4 =
        reinterpret_cast<const float4*>(in) + ((size_t)p * 512u + 2u * oy) * 128u + 2u * tx;

    // Front-batched loads: 8 independent LDG.128 (MLP_p1 = 8).
    const float4 r0a = __ldcs(in4 + 0);
    const float4 r0b = __ldcs(in4 + 1);
    const float4 r1a = __ldcs(in4 + 128);
    const float4 r1b = __ldcs(in4 + 129);
    const float4 r2a = __ldcs(in4 + 256);
    const float4 r2b = __ldcs(in4 + 257);
    const float4 r3a = __ldcs(in4 + 384);
    const float4 r3b = __ldcs(in4 + 385);

    float4 ll0, lh0, hl0, hh0, ll1, lh1, hl1, hh1;

    // --- output row oy (input rows 2oy, 2oy+1) ---
    {
        const float a = r0a.x, b = r0a.y, c = r1a.x, d = r1a.y;
        ll0.x = ( a + b + c + d) * 0.5f;  lh0.x = (-a - b + c + d) * 0.5f;
        hl0.x = (-a + b - c + d) * 0.5f;  hh0.x = ( a - b - c + d) * 0.5f;
    }
    {
        const float a = r0a.z, b = r0a.w, c = r1a.z, d = r1a.w;
        ll0.y = ( a + b + c + d) * 0.5f;  lh0.y = (-a - b + c + d) * 0.5f;
        hl0.y = (-a + b - c + d) * 0.5f;  hh0.y = ( a - b - c + d) * 0.5f;
    }
    {
        const float a = r0b.x, b = r0b.y, c = r1b.x, d = r1b.y;
        ll0.z = ( a + b + c + d) * 0.5f;  lh0.z = (-a - b + c + d) * 0.5f;
        hl0.z = (-a + b - c + d) * 0.5f;  hh0.z = ( a - b - c + d) * 0.5f;
    }
    {
        const float a = r0b.z, b = r0b.w, c = r1b.z, d = r1b.w;
        ll0.w = ( a + b + c + d) * 0.5f;  lh0.w = (-a - b + c + d) * 0.5f;
        hl0.w = (-a + b - c + d) * 0.5f;  hh0.w = ( a - b - c + d) * 0.5f;
    }

    // --- output row oy+1 (input rows 2oy+2, 2oy+3) ---
    {
        const float a = r2a.x, b = r2a.y, c = r3a.x, d = r3a.y;
        ll1.x = ( a + b + c + d) * 0.5f;  lh1.x = (-a - b + c + d) * 0.5f;
        hl1.x = (-a + b - c + d) * 0.5f;  hh1.x = ( a - b - c + d) * 0.5f;
    }
    {
        const float a = r2a.z, b = r2a.w, c = r3a.z, d = r3a.w;
        ll1.y = ( a + b + c + d) * 0.5f;  lh1.y = (-a - b + c + d) * 0.5f;
        hl1.y = (-a + b - c + d) * 0.5f;  hh1.y = ( a - b - c + d) * 0.5f;
    }
    {
        const float a = r2b.x, b = r2b.y, c = r3b.x, d = r3b.y;
        ll1.z = ( a + b + c + d) * 0.5f;  lh1.z = (-a - b + c + d) * 0.5f;
        hl1.z = (-a + b - c + d) * 0.5f;  hh1.z = ( a - b - c + d) * 0.5f;
    }
    {
        const float a = r2b.z, b = r2b.w, c = r3b.z, d = r3b.w;
        ll1.w = ( a + b + c + d) * 0.5f;  lh1.w = (-a - b + c + d) * 0.5f;
        hl1.w = (-a + b - c + d) * 0.5f;  hh1.w = ( a - b - c + d) * 0.5f;
    }

    // Output: element offset within a quadrant; multiple of 4 -> float4 aligned.
    const size_t qsize = (size_t)512u * 256u * 256u;               // 33,554,432
    const size_t obase = (((size_t)p * 256u + oy) * 256u) + 4u * tx;

    float* o0 = out + obase;
    __stcs(reinterpret_cast<float4*>(o0 + 0 * qsize),        ll0);
    __stcs(reinterpret_cast<float4*>(o0 + 0 * qsize + 256),  ll1);
    __stcs(reinterpret_cast<float4*>(o0 + 1 * qsize),        lh0);
    __stcs(reinterpret_cast<float4*>(o0 + 1 * qsize + 256),  lh1);
    __stcs(reinterpret_cast<float4*>(o0 + 2 * qsize),        hl0);
    __stcs(reinterpret_cast<float4*>(o0 + 2 * qsize + 256),  hl1);
    __stcs(reinterpret_cast<float4*>(o0 + 3 * qsize),        hh0);
    __stcs(reinterpret_cast<float4*>(o0 + 3 * qsize + 256),  hh1);
}

extern "C" void kernel_launch(void* const* d_in, const int* in_sizes, int n_in,
                              void* d_out, int out_size) {
    const float* x = (const float*)d_in[0];
    float* out = (float*)d_out;
    haar_dwt_kernel<<<16384, 256>>>(x, out);
}